// round 12
// baseline (speedup 1.0000x reference)
#include <cuda_runtime.h>
#include <cuda_fp16.h>
#include <cstdint>

#define DEVI __device__ __forceinline__

constexpr int Bb = 4, Ss = 2048, Dd = 1024;
constexpr int MROWS = Bb * Ss;   // 8192
constexpr int LF = 32;           // truncated FIR length (tail < 1e-9)

// ---------------- scratch (device globals; no runtime allocation) ----------
__device__ float  g_K[LF * Dd];                      // K[tau][d]
__device__ float  g_y[(size_t)MROWS * Dd];           // SSM output (f32)
__device__ __half g_gh[(size_t)MROWS * Dd];          // gelu(ln(y)) in fp16
__device__ __half g_Wh[(size_t)Dd * Dd];             // W_out in fp16

// ---------------- PTX helpers ----------------------------------------------
DEVI void cp16(uint32_t dst, const void* src) {
    asm volatile("cp.async.cg.shared.global [%0], [%1], 16;" :: "r"(dst), "l"(src));
}
DEVI void cp_commit() { asm volatile("cp.async.commit_group;" ::: "memory"); }
DEVI void cp_wait1()  { asm volatile("cp.async.wait_group 1;" ::: "memory"); }
DEVI uint32_t smem_u32(const void* p) {
    uint32_t a;
    asm("{ .reg .u64 t; cvta.to.shared.u64 t, %1; cvt.u32.u64 %0, t; }"
        : "=r"(a) : "l"(p));
    return a;
}
DEVI void ldsm4(uint32_t* r, uint32_t addr) {
    asm volatile("ldmatrix.sync.aligned.m8n8.x4.shared.b16 {%0,%1,%2,%3}, [%4];"
        : "=r"(r[0]), "=r"(r[1]), "=r"(r[2]), "=r"(r[3]) : "r"(addr));
}
DEVI void mma_f16(float* c, const uint32_t* a, const uint32_t* b) {
    asm volatile(
        "mma.sync.aligned.m16n8k16.row.col.f32.f16.f16.f32 "
        "{%0,%1,%2,%3}, {%4,%5,%6,%7}, {%8,%9}, {%0,%1,%2,%3};"
        : "+f"(c[0]), "+f"(c[1]), "+f"(c[2]), "+f"(c[3])
        : "r"(a[0]), "r"(a[1]), "r"(a[2]), "r"(a[3]), "r"(b[0]), "r"(b[1]));
}

// ============ 1) fused: W_out->fp16 (blocks 0..1023) + impulse response =====
__global__ void prep_kernel(const float* __restrict__ W,
                            const float* __restrict__ A, const float* __restrict__ Bm,
                            const float* __restrict__ Cm, const float* __restrict__ Dm) {
    if (blockIdx.x < 1024) {
        int idx = blockIdx.x * 256 + threadIdx.x;
        float4 v = ((const float4*)W)[idx];
        __half2 h0 = __floats2half2_rn(v.x, v.y);
        __half2 h1 = __floats2half2_rn(v.z, v.w);
        uint2 u;
        u.x = *(uint32_t*)&h0;
        u.y = *(uint32_t*)&h1;
        ((uint2*)g_Wh)[idx] = u;
        return;
    }
    int tid = threadIdx.x;
    int d  = (blockIdx.x - 1024) * 16 + (tid >> 4);
    int ln = tid & 15;

    const float4* A4 = (const float4*)(A + ((size_t)d * 16 + ln) * 16);
    float4 r0 = A4[0], r1 = A4[1], r2 = A4[2], r3 = A4[3];
    float a[16] = {r0.x, r0.y, r0.z, r0.w, r1.x, r1.y, r1.z, r1.w,
                   r2.x, r2.y, r2.z, r2.w, r3.x, r3.y, r3.z, r3.w};

    float v = Bm[d * 16 + ln];
    float c = Cm[d * 16 + ln];

    float s = c * v;
#pragma unroll
    for (int o = 8; o; o >>= 1) s += __shfl_xor_sync(0xffffffffu, s, o, 16);
    if (ln == 0) g_K[d] = s + Dm[d];

    for (int tau = 1; tau < LF; tau++) {
        float nv = 0.f;
#pragma unroll
        for (int m = 0; m < 16; m++)
            nv = fmaf(a[m], __shfl_sync(0xffffffffu, v, m, 16), nv);
        v = nv;
        s = c * v;
#pragma unroll
        for (int o = 8; o; o >>= 1) s += __shfl_xor_sync(0xffffffffu, s, o, 16);
        if (ln == 0) g_K[tau * Dd + d] = s;
    }
}

// ======================= 2) depthwise FIR convolution ========================
__global__ __launch_bounds__(256, 2)
void conv_kernel(const float* __restrict__ x) {
    int d    = blockIdx.x * 256 + threadIdx.x;
    int tile = blockIdx.y;
    int b  = tile >> 7;
    int t0 = (tile & 127) << 4;

    float k[LF];
#pragma unroll
    for (int t = 0; t < LF; t++) k[t] = g_K[t * Dd + d];

    float acc[16];
#pragma unroll
    for (int i = 0; i < 16; i++) acc[i] = 0.f;

    const float* xb = x + (size_t)b * Ss * Dd + d;
#pragma unroll
    for (int j = 0; j < LF + 15; j++) {
        int s = t0 - (LF - 1) + j;
        float xv = (s >= 0) ? xb[(size_t)s * Dd] : 0.f;
#pragma unroll
        for (int i = 0; i < 16; i++) {
            int tau = (LF - 1) + i - j;
            if (tau >= 0 && tau < LF) acc[i] = fmaf(k[tau], xv, acc[i]);
        }
    }
    float* yb = g_y + (size_t)b * Ss * Dd + d;
#pragma unroll
    for (int i = 0; i < 16; i++) yb[(size_t)(t0 + i) * Dd] = acc[i];
}

// ======================= 3) LayerNorm + exact GELU -> fp16 ==================
__global__ void ln_gelu_kernel(const float* __restrict__ lnw, const float* __restrict__ lnb) {
    __shared__ float red[16];
    int row = blockIdx.x;
    int tid = threadIdx.x;

    float4 v = ((const float4*)(g_y + (size_t)row * Dd))[tid];
    float s1 = v.x + v.y + v.z + v.w;
    float s2 = v.x * v.x + v.y * v.y + v.z * v.z + v.w * v.w;
#pragma unroll
    for (int o = 16; o; o >>= 1) {
        s1 += __shfl_xor_sync(~0u, s1, o);
        s2 += __shfl_xor_sync(~0u, s2, o);
    }
    int wid = tid >> 5;
    if ((tid & 31) == 0) { red[wid] = s1; red[8 + wid] = s2; }
    __syncthreads();
    if (tid < 32) {
        float aa = (tid < 8) ? red[tid] : 0.f;
        float bb = (tid < 8) ? red[8 + tid] : 0.f;
#pragma unroll
        for (int o = 4; o; o >>= 1) {
            aa += __shfl_xor_sync(~0u, aa, o);
            bb += __shfl_xor_sync(~0u, bb, o);
        }
        if (tid == 0) { red[0] = aa; red[1] = bb; }
    }
    __syncthreads();
    float mu   = red[0] * (1.f / Dd);
    float var  = red[1] * (1.f / Dd) - mu * mu;
    float rstd = rsqrtf(var + 1e-5f);

    float4 w = ((const float4*)lnw)[tid];
    float4 b = ((const float4*)lnb)[tid];
    float4 o;
    {
        float t;
        t = (v.x - mu) * rstd * w.x + b.x; o.x = 0.5f * t * (1.f + erff(t * 0.70710678118654752f));
        t = (v.y - mu) * rstd * w.y + b.y; o.y = 0.5f * t * (1.f + erff(t * 0.70710678118654752f));
        t = (v.z - mu) * rstd * w.z + b.z; o.z = 0.5f * t * (1.f + erff(t * 0.70710678118654752f));
        t = (v.w - mu) * rstd * w.w + b.w; o.w = 0.5f * t * (1.f + erff(t * 0.70710678118654752f));
    }
    __half2 h0 = __floats2half2_rn(o.x, o.y);
    __half2 h1 = __floats2half2_rn(o.z, o.w);
    uint2 u;
    u.x = *(uint32_t*)&h0;
    u.y = *(uint32_t*)&h1;
    ((uint2*)(g_gh + (size_t)row * Dd))[tid] = u;
}

// ======================= 4) fp16 mma GEMM (sw-pipelined) =====================
// out[m][n] = x[m][n] + b_out[n] + sum_k g[m][k] * W[n][k]
constexpr int BM = 128, BN = 128, BK = 64, STG = 3;
constexpr int A_BYTES = BM * 128;              // 16 KB
constexpr int STAGE_BYTES = 2 * A_BYTES;       // 32 KB
constexpr int SMEM_TOTAL = STG * STAGE_BYTES;  // 96 KB
constexpr int KTILES = Dd / BK;                // 16

__global__ __launch_bounds__(256, 2)
void gemm_kernel(const float* __restrict__ bo,
                 const float* __restrict__ X, float* __restrict__ out) {
    extern __shared__ char smem[];
    uint32_t sb = smem_u32(smem);
    int tid = threadIdx.x, wid = tid >> 5, lane = tid & 31;
    int n0 = blockIdx.x * BN, m0 = blockIdx.y * BM;
    int warp_m = wid >> 2, warp_n = wid & 3;   // 2 x 4 warps, 64x32 each

    // per-thread LDGSTS source/dst precompute (chunk c = tid + kb*256)
    int lm = tid >> 3, lcc = tid & 7;          // row-in-tile, 16B-chunk-in-row
    const __half* gA = g_gh + (size_t)(m0 + lm) * Dd + lcc * 8;
    const __half* gB = g_Wh + (size_t)(n0 + lm) * Dd + lcc * 8;
    uint32_t sA = lm * 128 + ((lcc * 16) ^ ((lm & 7) << 4));  // within A tile
    // (same pattern for B tile, offset by A_BYTES)

    float acc[4][4][4];
#pragma unroll
    for (int i = 0; i < 4; i++)
#pragma unroll
        for (int j = 0; j < 4; j++)
#pragma unroll
            for (int r = 0; r < 4; r++) acc[i][j][r] = 0.f;

    // prologue: stages 0,1 (full 8-chunk bursts)
#pragma unroll
    for (int s = 0; s < 2; s++) {
        uint32_t ab = sb + s * STAGE_BYTES;
#pragma unroll
        for (int t = 0; t < 4; t++) {
            cp16(ab + sA + (t * 32) * 128, gA + (size_t)s * BK + t * 32 * Dd);
            cp16(ab + A_BYTES + sA + (t * 32) * 128, gB + (size_t)s * BK + t * 32 * Dd);
        }
        cp_commit();
    }

    // ldmatrix per-lane addressing
    uint32_t xm   = (lane & 7) << 4;
    uint32_t arow = warp_m * 64 + (lane & 15);
    uint32_t akof = (lane >> 4) * 16;
    uint32_t brow = warp_n * 32 + (lane >> 4) * 8 + (lane & 7);
    uint32_t bkof = ((lane >> 3) & 1) * 16;

    int lr = lane >> 2, lc = lane & 3;

    for (int kt = 0; kt < KTILES; kt++) {
        cp_wait1();
        __syncthreads();

        uint32_t abase = sb + (kt % STG) * STAGE_BYTES;
        uint32_t bbase = abase + A_BYTES;
        uint32_t dstA  = sb + ((kt + 2) % STG) * STAGE_BYTES + sA;
        const __half* srcA = gA + (size_t)(kt + 2) * BK;
        const __half* srcB = gB + (size_t)(kt + 2) * BK;
        bool doload = (kt + 2 < KTILES);

        uint32_t af[2][4][4], bf[2][2][4];
        // preload kb=0 fragments
        {
            uint32_t ak = akof ^ xm, bk = bkof ^ xm;
#pragma unroll
            for (int mt = 0; mt < 4; mt++)
                ldsm4(af[0][mt], abase + (arow + mt * 16) * 128 + ak);
#pragma unroll
            for (int p = 0; p < 2; p++)
                ldsm4(bf[0][p], bbase + (brow + p * 16) * 128 + bk);
        }

#pragma unroll
        for (int kb = 0; kb < 4; kb++) {
            int cur = kb & 1, nxt = cur ^ 1;
            // prefetch kb+1 fragments (independent of this kb's MMAs)
            if (kb < 3) {
                uint32_t ak = ((kb + 1) * 32 + akof) ^ xm;
                uint32_t bk = ((kb + 1) * 32 + bkof) ^ xm;
#pragma unroll
                for (int mt = 0; mt < 4; mt++)
                    ldsm4(af[nxt][mt], abase + (arow + mt * 16) * 128 + ak);
#pragma unroll
                for (int p = 0; p < 2; p++)
                    ldsm4(bf[nxt][p], bbase + (brow + p * 16) * 128 + bk);
            }
            // 2 of the 8 next-stage LDGSTS chunks per kb group
            if (doload) {
                cp16(dstA + (kb * 32) * 128, srcA + (size_t)kb * 32 * Dd);
                cp16(dstA + A_BYTES + (kb * 32) * 128, srcB + (size_t)kb * 32 * Dd);
            }
            // 16 MMAs of kb
#pragma unroll
            for (int mt = 0; mt < 4; mt++)
#pragma unroll
                for (int nt = 0; nt < 4; nt++)
                    mma_f16(acc[mt][nt], af[cur][mt], bf[cur][nt >> 1] + (nt & 1) * 2);
        }
        cp_commit();
    }

    // fused epilogue: out = acc + X + b_out
#pragma unroll
    for (int mt = 0; mt < 4; mt++) {
        int row0 = m0 + warp_m * 64 + mt * 16 + lr;
#pragma unroll
        for (int nt = 0; nt < 4; nt++) {
            int col = n0 + warp_n * 32 + nt * 8 + lc * 2;
            float2 bv = *(const float2*)(bo + col);
            float2 x0 = *(const float2*)(X + (size_t)row0 * Dd + col);
            float2 x1 = *(const float2*)(X + (size_t)(row0 + 8) * Dd + col);
            float2 o0, o1;
            o0.x = acc[mt][nt][0] + x0.x + bv.x;
            o0.y = acc[mt][nt][1] + x0.y + bv.y;
            o1.x = acc[mt][nt][2] + x1.x + bv.x;
            o1.y = acc[mt][nt][3] + x1.y + bv.y;
            *(float2*)(out + (size_t)row0 * Dd + col) = o0;
            *(float2*)(out + (size_t)(row0 + 8) * Dd + col) = o1;
        }
    }
}

// ======================= launch =============================================
extern "C" void kernel_launch(void* const* d_in, const int* in_sizes, int n_in,
                              void* d_out, int out_size) {
    const float* x   = (const float*)d_in[0];
    const float* A   = (const float*)d_in[1];
    const float* Bm  = (const float*)d_in[2];
    const float* Cm  = (const float*)d_in[3];
    const float* Dm  = (const float*)d_in[4];
    const float* lnw = (const float*)d_in[5];
    const float* lnb = (const float*)d_in[6];
    const float* Wo  = (const float*)d_in[7];
    const float* bo  = (const float*)d_in[8];
    float* out = (float*)d_out;

    cudaFuncSetAttribute(gemm_kernel, cudaFuncAttributeMaxDynamicSharedMemorySize,
                         SMEM_TOTAL);

    prep_kernel<<<1024 + Dd / 16, 256>>>(Wo, A, Bm, Cm, Dm);
    conv_kernel<<<dim3(Dd / 256, MROWS / 16), 256>>>(x);
    ln_gelu_kernel<<<MROWS, 256>>>(lnw, lnb);
    gemm_kernel<<<dim3(Dd / BN, MROWS / BM), 256, SMEM_TOTAL>>>(bo, x, out);
}

// round 16
// speedup vs baseline: 1.0441x; 1.0441x over previous
#include <cuda_runtime.h>
#include <cuda_fp16.h>
#include <cstdint>

#define DEVI __device__ __forceinline__

constexpr int Bb = 4, Ss = 2048, Dd = 1024;
constexpr int MROWS = Bb * Ss;   // 8192
constexpr int LF = 32;           // truncated FIR length (tail < 1e-9)
constexpr int TROWS = 16;        // time-rows per fused block
constexpr int CL_SMEM = TROWS * Dd * 4 + 2 * TROWS * 2 * 4;  // 65664 B (dynamic)

// ---------------- scratch (device globals; no runtime allocation) ----------
__device__ float  g_K[LF * Dd];                      // K[tau][d]
__device__ __half g_gh[(size_t)MROWS * Dd];          // gelu(ln(y)) in fp16
__device__ __half g_Wh[(size_t)Dd * Dd];             // W_out in fp16

// ---------------- PTX helpers ----------------------------------------------
DEVI void cp16(uint32_t dst, const void* src) {
    asm volatile("cp.async.cg.shared.global [%0], [%1], 16;" :: "r"(dst), "l"(src));
}
DEVI void cp_commit() { asm volatile("cp.async.commit_group;" ::: "memory"); }
DEVI void cp_wait1()  { asm volatile("cp.async.wait_group 1;" ::: "memory"); }
DEVI uint32_t smem_u32(const void* p) {
    uint32_t a;
    asm("{ .reg .u64 t; cvta.to.shared.u64 t, %1; cvt.u32.u64 %0, t; }"
        : "=r"(a) : "l"(p));
    return a;
}
DEVI void ldsm4(uint32_t* r, uint32_t addr) {
    asm volatile("ldmatrix.sync.aligned.m8n8.x4.shared.b16 {%0,%1,%2,%3}, [%4];"
        : "=r"(r[0]), "=r"(r[1]), "=r"(r[2]), "=r"(r[3]) : "r"(addr));
}
DEVI void mma_f16(float* c, const uint32_t* a, const uint32_t* b) {
    asm volatile(
        "mma.sync.aligned.m16n8k16.row.col.f32.f16.f16.f32 "
        "{%0,%1,%2,%3}, {%4,%5,%6,%7}, {%8,%9}, {%0,%1,%2,%3};"
        : "+f"(c[0]), "+f"(c[1]), "+f"(c[2]), "+f"(c[3])
        : "r"(a[0]), "r"(a[1]), "r"(a[2]), "r"(a[3]), "r"(b[0]), "r"(b[1]));
}

// ============ 1) fused: W_out->fp16 (blocks 0..1023) + impulse response =====
__global__ void prep_kernel(const float* __restrict__ W,
                            const float* __restrict__ A, const float* __restrict__ Bm,
                            const float* __restrict__ Cm, const float* __restrict__ Dm) {
    if (blockIdx.x < 1024) {
        int idx = blockIdx.x * 256 + threadIdx.x;
        float4 v = ((const float4*)W)[idx];
        __half2 h0 = __floats2half2_rn(v.x, v.y);
        __half2 h1 = __floats2half2_rn(v.z, v.w);
        uint2 u;
        u.x = *(uint32_t*)&h0;
        u.y = *(uint32_t*)&h1;
        ((uint2*)g_Wh)[idx] = u;
        return;
    }
    int tid = threadIdx.x;
    int d  = (blockIdx.x - 1024) * 16 + (tid >> 4);
    int ln = tid & 15;

    const float4* A4 = (const float4*)(A + ((size_t)d * 16 + ln) * 16);
    float4 r0 = A4[0], r1 = A4[1], r2 = A4[2], r3 = A4[3];
    float a[16] = {r0.x, r0.y, r0.z, r0.w, r1.x, r1.y, r1.z, r1.w,
                   r2.x, r2.y, r2.z, r2.w, r3.x, r3.y, r3.z, r3.w};

    float v = Bm[d * 16 + ln];
    float c = Cm[d * 16 + ln];

    float s = c * v;
#pragma unroll
    for (int o = 8; o; o >>= 1) s += __shfl_xor_sync(0xffffffffu, s, o, 16);
    if (ln == 0) g_K[d] = s + Dm[d];

    for (int tau = 1; tau < LF; tau++) {
        float nv = 0.f;
#pragma unroll
        for (int m = 0; m < 16; m++)
            nv = fmaf(a[m], __shfl_sync(0xffffffffu, v, m, 16), nv);
        v = nv;
        s = c * v;
#pragma unroll
        for (int o = 8; o; o >>= 1) s += __shfl_xor_sync(0xffffffffu, s, o, 16);
        if (ln == 0) g_K[tau * Dd + d] = s;
    }
}

// ========== 2) fused depthwise FIR conv + LayerNorm + GELU -> fp16 ==========
// block: 16 time-rows x all 1024 channels. conv per thread (channel = tid),
// smem transpose, LN across channels, exact-erf GELU, fp16 store.
// smem is DYNAMIC (65,664 B > 48 KB static limit).
__global__ __launch_bounds__(1024, 1)
void conv_ln_kernel(const float* __restrict__ x,
                    const float* __restrict__ lnw, const float* __restrict__ lnb) {
    extern __shared__ float smem_cl[];
    float* sy   = smem_cl;                       // TROWS*Dd floats (64 KB)
    float* red1 = smem_cl + TROWS * Dd;          // TROWS*2 floats
    float* red2 = red1 + TROWS * 2;              // TROWS*2 floats

    int tid  = threadIdx.x;                // channel
    int tile = blockIdx.x;                 // 512 tiles
    int b  = tile >> 7;                    // Ss/TROWS = 128 tiles per batch
    int t0 = (tile & 127) * TROWS;

    // ---- conv (R3-proven structure) ----
    float k[LF];
#pragma unroll
    for (int t = 0; t < LF; t++) k[t] = g_K[t * Dd + tid];

    float acc[TROWS];
#pragma unroll
    for (int i = 0; i < TROWS; i++) acc[i] = 0.f;

    const float* xb = x + (size_t)b * Ss * Dd + tid;
#pragma unroll
    for (int j = 0; j < LF + TROWS - 1; j++) {
        int s = t0 - (LF - 1) + j;
        float xv = (s >= 0) ? xb[(size_t)s * Dd] : 0.f;
#pragma unroll
        for (int i = 0; i < TROWS; i++) {
            int tau = (LF - 1) + i - j;
            if (tau >= 0 && tau < LF) acc[i] = fmaf(k[tau], xv, acc[i]);
        }
    }
#pragma unroll
    for (int i = 0; i < TROWS; i++) sy[i * Dd + tid] = acc[i];
    __syncthreads();

    // ---- LN: row r, 64 threads/row; thread owns chunks 4j + 256i ----
    int r = tid >> 6, j = tid & 63, p = (tid >> 5) & 1;
    float4 v[4];
    float s1 = 0.f, s2 = 0.f;
#pragma unroll
    for (int i = 0; i < 4; i++) {
        v[i] = *(const float4*)(sy + r * Dd + 4 * j + 256 * i);
        s1 += v[i].x + v[i].y + v[i].z + v[i].w;
        s2 += v[i].x * v[i].x + v[i].y * v[i].y + v[i].z * v[i].z + v[i].w * v[i].w;
    }
#pragma unroll
    for (int o = 16; o; o >>= 1) {
        s1 += __shfl_xor_sync(~0u, s1, o);
        s2 += __shfl_xor_sync(~0u, s2, o);
    }
    if ((tid & 31) == 0) { red1[r * 2 + p] = s1; red2[r * 2 + p] = s2; }
    __syncthreads();
    float S1 = red1[r * 2] + red1[r * 2 + 1];
    float S2 = red2[r * 2] + red2[r * 2 + 1];
    float mu   = S1 * (1.f / Dd);
    float var  = S2 * (1.f / Dd) - mu * mu;
    float rstd = rsqrtf(var + 1e-5f);

    // ---- GELU + fp16 store ----
    size_t grow = (size_t)(b * Ss + t0 + r) * Dd;
#pragma unroll
    for (int i = 0; i < 4; i++) {
        int col = 4 * j + 256 * i;
        float4 w = *(const float4*)(lnw + col);
        float4 bb = *(const float4*)(lnb + col);
        float4 o;
        float t;
        t = (v[i].x - mu) * rstd * w.x + bb.x; o.x = 0.5f * t * (1.f + erff(t * 0.70710678118654752f));
        t = (v[i].y - mu) * rstd * w.y + bb.y; o.y = 0.5f * t * (1.f + erff(t * 0.70710678118654752f));
        t = (v[i].z - mu) * rstd * w.z + bb.z; o.z = 0.5f * t * (1.f + erff(t * 0.70710678118654752f));
        t = (v[i].w - mu) * rstd * w.w + bb.w; o.w = 0.5f * t * (1.f + erff(t * 0.70710678118654752f));
        __half2 h0 = __floats2half2_rn(o.x, o.y);
        __half2 h1 = __floats2half2_rn(o.z, o.w);
        uint2 u;
        u.x = *(uint32_t*)&h0;
        u.y = *(uint32_t*)&h1;
        *(uint2*)(g_gh + grow + col) = u;
    }
}

// ======================= 3) fp16 mma GEMM (sw-pipelined) =====================
// out[m][n] = x[m][n] + b_out[n] + sum_k g[m][k] * W[n][k]
constexpr int BM = 128, BN = 128, BK = 64, STG = 3;
constexpr int A_BYTES = BM * 128;              // 16 KB
constexpr int STAGE_BYTES = 2 * A_BYTES;       // 32 KB
constexpr int SMEM_TOTAL = STG * STAGE_BYTES;  // 96 KB
constexpr int KTILES = Dd / BK;                // 16

__global__ __launch_bounds__(256, 2)
void gemm_kernel(const float* __restrict__ bo,
                 const float* __restrict__ X, float* __restrict__ out) {
    extern __shared__ char smem[];
    uint32_t sb = smem_u32(smem);
    int tid = threadIdx.x, wid = tid >> 5, lane = tid & 31;
    int n0 = blockIdx.x * BN, m0 = blockIdx.y * BM;
    int warp_m = wid >> 2, warp_n = wid & 3;   // 2 x 4 warps, 64x32 each

    int lm = tid >> 3, lcc = tid & 7;
    const __half* gA = g_gh + (size_t)(m0 + lm) * Dd + lcc * 8;
    const __half* gB = g_Wh + (size_t)(n0 + lm) * Dd + lcc * 8;
    uint32_t sA = lm * 128 + ((lcc * 16) ^ ((lm & 7) << 4));

    float acc[4][4][4];
#pragma unroll
    for (int i = 0; i < 4; i++)
#pragma unroll
        for (int j = 0; j < 4; j++)
#pragma unroll
            for (int r = 0; r < 4; r++) acc[i][j][r] = 0.f;

#pragma unroll
    for (int s = 0; s < 2; s++) {
        uint32_t ab = sb + s * STAGE_BYTES;
#pragma unroll
        for (int t = 0; t < 4; t++) {
            cp16(ab + sA + (t * 32) * 128, gA + (size_t)s * BK + t * 32 * Dd);
            cp16(ab + A_BYTES + sA + (t * 32) * 128, gB + (size_t)s * BK + t * 32 * Dd);
        }
        cp_commit();
    }

    uint32_t xm   = (lane & 7) << 4;
    uint32_t arow = warp_m * 64 + (lane & 15);
    uint32_t akof = (lane >> 4) * 16;
    uint32_t brow = warp_n * 32 + (lane >> 4) * 8 + (lane & 7);
    uint32_t bkof = ((lane >> 3) & 1) * 16;

    int lr = lane >> 2, lc = lane & 3;

    for (int kt = 0; kt < KTILES; kt++) {
        cp_wait1();
        __syncthreads();

        uint32_t abase = sb + (kt % STG) * STAGE_BYTES;
        uint32_t bbase = abase + A_BYTES;
        uint32_t dstA  = sb + ((kt + 2) % STG) * STAGE_BYTES + sA;
        const __half* srcA = gA + (size_t)(kt + 2) * BK;
        const __half* srcB = gB + (size_t)(kt + 2) * BK;
        bool doload = (kt + 2 < KTILES);

        uint32_t af[2][4][4], bf[2][2][4];
        {
            uint32_t ak = akof ^ xm, bk = bkof ^ xm;
#pragma unroll
            for (int mt = 0; mt < 4; mt++)
                ldsm4(af[0][mt], abase + (arow + mt * 16) * 128 + ak);
#pragma unroll
            for (int p = 0; p < 2; p++)
                ldsm4(bf[0][p], bbase + (brow + p * 16) * 128 + bk);
        }

#pragma unroll
        for (int kb = 0; kb < 4; kb++) {
            int cur = kb & 1, nxt = cur ^ 1;
            if (kb < 3) {
                uint32_t ak = ((kb + 1) * 32 + akof) ^ xm;
                uint32_t bk = ((kb + 1) * 32 + bkof) ^ xm;
#pragma unroll
                for (int mt = 0; mt < 4; mt++)
                    ldsm4(af[nxt][mt], abase + (arow + mt * 16) * 128 + ak);
#pragma unroll
                for (int p = 0; p < 2; p++)
                    ldsm4(bf[nxt][p], bbase + (brow + p * 16) * 128 + bk);
            }
            if (doload) {
                cp16(dstA + (kb * 32) * 128, srcA + (size_t)kb * 32 * Dd);
                cp16(dstA + A_BYTES + (kb * 32) * 128, srcB + (size_t)kb * 32 * Dd);
            }
#pragma unroll
            for (int mt = 0; mt < 4; mt++)
#pragma unroll
                for (int nt = 0; nt < 4; nt++)
                    mma_f16(acc[mt][nt], af[cur][mt], bf[cur][nt >> 1] + (nt & 1) * 2);
        }
        cp_commit();
    }

    // fused epilogue: out = acc + X + b_out
#pragma unroll
    for (int mt = 0; mt < 4; mt++) {
        int row0 = m0 + warp_m * 64 + mt * 16 + lr;
#pragma unroll
        for (int nt = 0; nt < 4; nt++) {
            int col = n0 + warp_n * 32 + nt * 8 + lc * 2;
            float2 bv = *(const float2*)(bo + col);
            float2 x0 = *(const float2*)(X + (size_t)row0 * Dd + col);
            float2 x1 = *(const float2*)(X + (size_t)(row0 + 8) * Dd + col);
            float2 o0, o1;
            o0.x = acc[mt][nt][0] + x0.x + bv.x;
            o0.y = acc[mt][nt][1] + x0.y + bv.y;
            o1.x = acc[mt][nt][2] + x1.x + bv.x;
            o1.y = acc[mt][nt][3] + x1.y + bv.y;
            *(float2*)(out + (size_t)row0 * Dd + col) = o0;
            *(float2*)(out + (size_t)(row0 + 8) * Dd + col) = o1;
        }
    }
}

// ======================= launch =============================================
extern "C" void kernel_launch(void* const* d_in, const int* in_sizes, int n_in,
                              void* d_out, int out_size) {
    const float* x   = (const float*)d_in[0];
    const float* A   = (const float*)d_in[1];
    const float* Bm  = (const float*)d_in[2];
    const float* Cm  = (const float*)d_in[3];
    const float* Dm  = (const float*)d_in[4];
    const float* lnw = (const float*)d_in[5];
    const float* lnb = (const float*)d_in[6];
    const float* Wo  = (const float*)d_in[7];
    const float* bo  = (const float*)d_in[8];
    float* out = (float*)d_out;

    cudaFuncSetAttribute(gemm_kernel, cudaFuncAttributeMaxDynamicSharedMemorySize,
                         SMEM_TOTAL);
    cudaFuncSetAttribute(conv_ln_kernel, cudaFuncAttributeMaxDynamicSharedMemorySize,
                         CL_SMEM);

    prep_kernel<<<1024 + Dd / 16, 256>>>(Wo, A, Bm, Cm, Dm);
    conv_ln_kernel<<<MROWS / TROWS, 1024, CL_SMEM>>>(x, lnw, lnb);
    gemm_kernel<<<dim3(Dd / BN, MROWS / BM), 256, SMEM_TOTAL>>>(bo, x, out);
}